// round 1
// baseline (speedup 1.0000x reference)
#include <cuda_runtime.h>

// Problem constants (fixed by the reference)
#define NB 4
#define NH 16
#define NL 2048
#define ND 64
#define BQ 16          // query rows per CTA
#define KT 128         // K/V tile rows per iteration
#define KROW 68        // padded SMEM row (floats): 68 % 32 == 4 -> conflict-free strided access
#define NEGV (-1.0e9f)

// SMEM layout (floats):
//   Ss : BQ*NL   = 32768   score / prob block (128 KB)
//   Qs : BQ*KROW = 1088    Q tile (pre-scaled by 1/sqrt(D))
//   Ks : KT*KROW = 8704    K tile (reused as V tile)
//   Ms : NL      = 2048    mask row pre-multiplied by -1e9
static const int SMEM_BYTES = (BQ * NL + BQ * KROW + KT * KROW + NL) * 4;  // 178432 B

__global__ __launch_bounds__(256, 1)
void attn_fused_kernel(const float* __restrict__ gq,
                       const float* __restrict__ gk,
                       const float* __restrict__ gv,
                       const float* __restrict__ gmask,
                       float* __restrict__ gout,
                       float* __restrict__ gattn)
{
    extern __shared__ float sm[];
    float* Ss = sm;
    float* Qs = Ss + BQ * NL;
    float* Ks = Qs + BQ * KROW;
    float* Ms = Ks + KT * KROW;
    float4* Ss4 = reinterpret_cast<float4*>(Ss);

    const int tid = threadIdx.x;
    const int qt = blockIdx.x;
    const int h  = blockIdx.y;
    const int b  = blockIdx.z;
    const long bh = (long)b * NH + h;

    const float* qp = gq + (bh * NL + (long)qt * BQ) * ND;
    const float* kp = gk + bh * NL * ND;
    const float* vp = gv + bh * NL * ND;

    // ---- mask row, pre-multiplied by -1e9 ----
    for (int i = tid; i < NL; i += 256)
        Ms[i] = gmask[(long)b * NL + i] * NEGV;

    // ---- Q tile, pre-scaled by 1/sqrt(64) = 0.125 ----
    {
        const int r = tid >> 4;
        const int c = (tid & 15) << 2;
        float4 t = *reinterpret_cast<const float4*>(qp + r * ND + c);
        float* d = Qs + r * KROW + c;
        d[0] = t.x * 0.125f; d[1] = t.y * 0.125f;
        d[2] = t.z * 0.125f; d[3] = t.w * 0.125f;
    }
    __syncthreads();

    const int kg = tid & 31;        // k-group (strided columns kg, kg+32, kg+64, kg+96)
    const int qg = tid >> 5;        // warp id == q pair id
    const int q0 = qg * 2, q1 = q0 + 1;
    const int lr = tid >> 4;        // tile-load row helper
    const int lc = (tid & 15) << 2; // tile-load col helper

    // =========================== S = (Q/8) K^T + mask*NEG ===========================
    for (int kt = 0; kt < NL; kt += KT) {
        #pragma unroll
        for (int rr = 0; rr < KT; rr += 16) {
            float4 t = *reinterpret_cast<const float4*>(kp + (long)(kt + rr + lr) * ND + lc);
            float* d = Ks + (rr + lr) * KROW + lc;
            d[0] = t.x; d[1] = t.y; d[2] = t.z; d[3] = t.w;
        }
        __syncthreads();

        float acc[2][4];
        #pragma unroll
        for (int i = 0; i < 2; i++)
            #pragma unroll
            for (int j = 0; j < 4; j++)
                acc[i][j] = 0.0f;

        #pragma unroll
        for (int dd = 0; dd < ND / 4; dd++) {
            const float4 a0 = *reinterpret_cast<const float4*>(Qs + q0 * KROW + dd * 4);
            const float4 a1 = *reinterpret_cast<const float4*>(Qs + q1 * KROW + dd * 4);
            #pragma unroll
            for (int j = 0; j < 4; j++) {
                const float4 kb = *reinterpret_cast<const float4*>(Ks + (kg + 32 * j) * KROW + dd * 4);
                acc[0][j] += a0.x * kb.x + a0.y * kb.y + a0.z * kb.z + a0.w * kb.w;
                acc[1][j] += a1.x * kb.x + a1.y * kb.y + a1.z * kb.z + a1.w * kb.w;
            }
        }

        #pragma unroll
        for (int j = 0; j < 4; j++) {
            const int kc = kt + kg + 32 * j;
            const float mz = Ms[kc];
            Ss[q0 * NL + kc] = acc[0][j] + mz;
            Ss[q1 * NL + kc] = acc[1][j] + mz;
        }
        __syncthreads();
    }

    // =========================== softmax rows + write attn ===========================
    const int lane = tid & 31;
    float4* gattn4 = reinterpret_cast<float4*>(gattn);

    #pragma unroll
    for (int rr = 0; rr < 2; rr++) {
        const int r = qg * 2 + rr;
        float4 vals[16];
        float mx = -3.4e38f;
        #pragma unroll
        for (int i = 0; i < 16; i++) {
            vals[i] = Ss4[r * (NL / 4) + lane + i * 32];
            mx = fmaxf(mx, fmaxf(fmaxf(vals[i].x, vals[i].y), fmaxf(vals[i].z, vals[i].w)));
        }
        #pragma unroll
        for (int o = 16; o; o >>= 1) mx = fmaxf(mx, __shfl_xor_sync(0xffffffffu, mx, o));

        float sum = 0.0f;
        #pragma unroll
        for (int i = 0; i < 16; i++) {
            vals[i].x = __expf(vals[i].x - mx);
            vals[i].y = __expf(vals[i].y - mx);
            vals[i].z = __expf(vals[i].z - mx);
            vals[i].w = __expf(vals[i].w - mx);
            sum += (vals[i].x + vals[i].y) + (vals[i].z + vals[i].w);
        }
        #pragma unroll
        for (int o = 16; o; o >>= 1) sum += __shfl_xor_sync(0xffffffffu, sum, o);
        const float inv = 1.0f / sum;

        const long arow = (bh * NL + (long)qt * BQ + r) * (NL / 4);
        #pragma unroll
        for (int i = 0; i < 16; i++) {
            float4 p;
            p.x = vals[i].x * inv; p.y = vals[i].y * inv;
            p.z = vals[i].z * inv; p.w = vals[i].w * inv;
            Ss4[r * (NL / 4) + lane + i * 32] = p;
            if (gattn4) gattn4[arow + lane + i * 32] = p;
        }
    }
    __syncthreads();

    // =========================== O = P V ===========================
    const int d0 = lane;
    const int d1 = lane + 32;
    float o00 = 0.f, o01 = 0.f, o10 = 0.f, o11 = 0.f;

    for (int vt = 0; vt < NL; vt += KT) {
        #pragma unroll
        for (int rr = 0; rr < KT; rr += 16) {
            float4 t = *reinterpret_cast<const float4*>(vp + (long)(vt + rr + lr) * ND + lc);
            float* d = Ks + (rr + lr) * KROW + lc;
            d[0] = t.x; d[1] = t.y; d[2] = t.z; d[3] = t.w;
        }
        __syncthreads();

        #pragma unroll 8
        for (int kk = 0; kk < KT; kk += 4) {
            const float4 p0 = Ss4[q0 * (NL / 4) + ((vt + kk) >> 2)];
            const float4 p1 = Ss4[q1 * (NL / 4) + ((vt + kk) >> 2)];
            const float* vr = Ks + kk * KROW;
            o00 += p0.x * vr[d0];                o01 += p0.x * vr[d1];
            o10 += p1.x * vr[d0];                o11 += p1.x * vr[d1];
            o00 += p0.y * vr[KROW + d0];         o01 += p0.y * vr[KROW + d1];
            o10 += p1.y * vr[KROW + d0];         o11 += p1.y * vr[KROW + d1];
            o00 += p0.z * vr[2 * KROW + d0];     o01 += p0.z * vr[2 * KROW + d1];
            o10 += p1.z * vr[2 * KROW + d0];     o11 += p1.z * vr[2 * KROW + d1];
            o00 += p0.w * vr[3 * KROW + d0];     o01 += p0.w * vr[3 * KROW + d1];
            o10 += p1.w * vr[3 * KROW + d0];     o11 += p1.w * vr[3 * KROW + d1];
        }
        __syncthreads();
    }

    float* op = gout + (bh * NL + (long)qt * BQ) * ND;
    op[q0 * ND + d0] = o00;
    op[q0 * ND + d1] = o01;
    op[q1 * ND + d0] = o10;
    op[q1 * ND + d1] = o11;
}

extern "C" void kernel_launch(void* const* d_in, const int* in_sizes, int n_in,
                              void* d_out, int out_size)
{
    (void)in_sizes; (void)n_in;
    const float* q    = (const float*)d_in[0];
    const float* k    = (const float*)d_in[1];
    const float* v    = (const float*)d_in[2];
    const float* mask = (const float*)d_in[3];
    float* out = (float*)d_out;

    const long OUT_ELEMS  = (long)NB * NH * NL * ND;   //   8,388,608
    const long ATTN_ELEMS = (long)NB * NH * NL * NL;   // 268,435,456
    float* attn = ((long)out_size >= OUT_ELEMS + ATTN_ELEMS) ? (out + OUT_ELEMS) : nullptr;

    cudaFuncSetAttribute(attn_fused_kernel,
                         cudaFuncAttributeMaxDynamicSharedMemorySize, SMEM_BYTES);

    dim3 grid(NL / BQ, NH, NB);
    attn_fused_kernel<<<grid, 256, SMEM_BYTES>>>(q, k, v, mask, out, attn);
}

// round 3
// speedup vs baseline: 2.9442x; 2.9442x over previous
#include <cuda_runtime.h>
#include <cuda_bf16.h>
#include <cstdint>

#define NB 4
#define NH 16
#define NL 2048
#define ND 64
#define NEGV (-1.0e9f)

// ===================== helpers =====================
__device__ __forceinline__ uint32_t smem_u32(const void* p) {
    uint32_t a;
    asm("{ .reg .u64 t; cvta.to.shared.u64 t, %1; cvt.u32.u64 %0, t; }" : "=r"(a) : "l"(p));
    return a;
}

__device__ __forceinline__ void ldmx4(uint32_t addr, uint32_t r[4]) {
    asm volatile("ldmatrix.sync.aligned.m8n8.x4.shared.b16 {%0,%1,%2,%3}, [%4];"
                 : "=r"(r[0]), "=r"(r[1]), "=r"(r[2]), "=r"(r[3]) : "r"(addr));
}
__device__ __forceinline__ void ldmx4t(uint32_t addr, uint32_t r[4]) {
    asm volatile("ldmatrix.sync.aligned.m8n8.x4.trans.shared.b16 {%0,%1,%2,%3}, [%4];"
                 : "=r"(r[0]), "=r"(r[1]), "=r"(r[2]), "=r"(r[3]) : "r"(addr));
}
__device__ __forceinline__ void mma_bf16(float d[4], const uint32_t a[4], const uint32_t b[2]) {
    asm volatile(
        "mma.sync.aligned.m16n8k16.row.col.f32.bf16.bf16.f32 "
        "{%0,%1,%2,%3}, {%4,%5,%6,%7}, {%8,%9}, {%0,%1,%2,%3};"
        : "+f"(d[0]), "+f"(d[1]), "+f"(d[2]), "+f"(d[3])
        : "r"(a[0]), "r"(a[1]), "r"(a[2]), "r"(a[3]), "r"(b[0]), "r"(b[1]));
}

__device__ __forceinline__ uint32_t pack2(__nv_bfloat16 x, __nv_bfloat16 y) {
    __nv_bfloat162 t; t.x = x; t.y = y;
    return *reinterpret_cast<uint32_t*>(&t);
}
// split float4 into bf16 hi (uint2) and bf16 residual lo (uint2)
__device__ __forceinline__ void cvt_hilo(float4 t, uint2& hi, uint2& lo) {
    __nv_bfloat16 h0 = __float2bfloat16(t.x), h1 = __float2bfloat16(t.y);
    __nv_bfloat16 h2 = __float2bfloat16(t.z), h3 = __float2bfloat16(t.w);
    hi.x = pack2(h0, h1); hi.y = pack2(h2, h3);
    lo.x = pack2(__float2bfloat16(t.x - __bfloat162float(h0)),
                 __float2bfloat16(t.y - __bfloat162float(h1)));
    lo.y = pack2(__float2bfloat16(t.z - __bfloat162float(h2)),
                 __float2bfloat16(t.w - __bfloat162float(h3)));
}

// ===================== K1: logits = (Q/8)K^T + mask*NEG =====================
#define K1_STR 72   // bf16 elems per row (144B: 16B-aligned, conflict-free ldmatrix)
static const int K1_SMEM = 512 + 4 * 128 * K1_STR * 2;  // 74240 B

__global__ __launch_bounds__(256, 1)
void k1_logits(const float* __restrict__ gq, const float* __restrict__ gk,
               const float* __restrict__ gmask, float* __restrict__ glog)
{
    extern __shared__ char smem[];
    float* Msk = (float*)smem;
    char* sQhi = smem + 512;
    char* sQlo = sQhi + 128 * K1_STR * 2;
    char* sKhi = sQlo + 128 * K1_STR * 2;
    char* sKlo = sKhi + 128 * K1_STR * 2;

    const int tid = threadIdx.x, lane = tid & 31, wid = tid >> 5;
    const int nt = blockIdx.x, qt = blockIdx.y, bh = blockIdx.z, b = bh >> 4;

    if (tid < 128) Msk[tid] = gmask[b * NL + nt * 128 + tid] * NEGV;

    const float* qp = gq + ((long)bh * NL + qt * 128) * ND;
    const float* kp = gk + ((long)bh * NL + nt * 128) * ND;

    for (int i = tid; i < 2048; i += 256) {  // 128 rows x 16 float4
        const int row = i >> 4, c4 = (i & 15) << 2;
        const int idx = row * K1_STR + c4;
        float4 tq = *(const float4*)(qp + row * ND + c4);
        tq.x *= 0.125f; tq.y *= 0.125f; tq.z *= 0.125f; tq.w *= 0.125f;
        uint2 hi, lo;
        cvt_hilo(tq, hi, lo);
        *(uint2*)(sQhi + idx * 2) = hi; *(uint2*)(sQlo + idx * 2) = lo;
        float4 tk = *(const float4*)(kp + row * ND + c4);
        cvt_hilo(tk, hi, lo);
        *(uint2*)(sKhi + idx * 2) = hi; *(uint2*)(sKlo + idx * 2) = lo;
    }
    __syncthreads();

    const int wm = wid >> 2, wn = wid & 3;
    float d[4][4][4];
    #pragma unroll
    for (int mi = 0; mi < 4; mi++)
        #pragma unroll
        for (int ni = 0; ni < 4; ni++)
            #pragma unroll
            for (int j = 0; j < 4; j++) d[mi][ni][j] = 0.0f;

    const uint32_t qhU = smem_u32(sQhi), qlU = smem_u32(sQlo);
    const uint32_t khU = smem_u32(sKhi), klU = smem_u32(sKlo);
    const int arow = lane & 15, acol = (lane >> 4) << 3;            // A/trans pattern
    const int brow = (lane & 7) + ((lane >> 4) << 3);               // B non-trans pattern
    const int bcol = ((lane >> 3) & 1) << 3;

    #pragma unroll
    for (int ks = 0; ks < 4; ks++) {
        const int k0 = ks * 16;
        uint32_t ah[4][4], al[4][4];
        #pragma unroll
        for (int mi = 0; mi < 4; mi++) {
            const uint32_t off = (uint32_t)((wm * 64 + mi * 16 + arow) * K1_STR + k0 + acol) * 2;
            ldmx4(qhU + off, ah[mi]);
            ldmx4(qlU + off, al[mi]);
        }
        uint32_t bh2[4][2], bl2[4][2];
        #pragma unroll
        for (int nb = 0; nb < 2; nb++) {
            const uint32_t off = (uint32_t)((wn * 32 + nb * 16 + brow) * K1_STR + k0 + bcol) * 2;
            uint32_t r[4];
            ldmx4(khU + off, r);
            bh2[2 * nb][0] = r[0]; bh2[2 * nb][1] = r[1];
            bh2[2 * nb + 1][0] = r[2]; bh2[2 * nb + 1][1] = r[3];
            ldmx4(klU + off, r);
            bl2[2 * nb][0] = r[0]; bl2[2 * nb][1] = r[1];
            bl2[2 * nb + 1][0] = r[2]; bl2[2 * nb + 1][1] = r[3];
        }
        #pragma unroll
        for (int mi = 0; mi < 4; mi++)
            #pragma unroll
            for (int ni = 0; ni < 4; ni++) {
                mma_bf16(d[mi][ni], ah[mi], bh2[ni]);
                mma_bf16(d[mi][ni], ah[mi], bl2[ni]);
                mma_bf16(d[mi][ni], al[mi], bh2[ni]);
            }
    }
    __syncthreads();

    // stage through smem for coalesced store (stride 132 floats)
    float* Sbuf = (float*)(smem + 512);
    #pragma unroll
    for (int mi = 0; mi < 4; mi++)
        #pragma unroll
        for (int ni = 0; ni < 4; ni++) {
            const int r0 = wm * 64 + mi * 16 + (lane >> 2);
            const int c0 = wn * 32 + ni * 8 + ((lane & 3) << 1);
            Sbuf[r0 * 132 + c0]     = d[mi][ni][0];
            Sbuf[r0 * 132 + c0 + 1] = d[mi][ni][1];
            Sbuf[(r0 + 8) * 132 + c0]     = d[mi][ni][2];
            Sbuf[(r0 + 8) * 132 + c0 + 1] = d[mi][ni][3];
        }
    __syncthreads();

    const long gbase = ((long)bh * NL + qt * 128) * NL + nt * 128;
    for (int i = tid; i < 4096; i += 256) {  // 128 rows x 32 float4
        const int row = i >> 5, c4 = (i & 31) << 2;
        float4 v = *(float4*)&Sbuf[row * 132 + c4];
        const float4 m = *(float4*)&Msk[c4];
        v.x += m.x; v.y += m.y; v.z += m.z; v.w += m.w;
        *(float4*)&glog[gbase + (long)row * NL + c4] = v;
    }
}

// ===================== K2: in-place row softmax =====================
__global__ __launch_bounds__(256)
void k2_softmax(float* __restrict__ p)
{
    __shared__ float red[8];
    const int tid = threadIdx.x, wid = tid >> 5, lid = tid & 31;
    float4* row = (float4*)(p + (long)blockIdx.x * NL);

    float4 v[2];
    v[0] = row[tid];
    v[1] = row[tid + 256];

    float mx = fmaxf(fmaxf(fmaxf(v[0].x, v[0].y), fmaxf(v[0].z, v[0].w)),
                     fmaxf(fmaxf(v[1].x, v[1].y), fmaxf(v[1].z, v[1].w)));
    #pragma unroll
    for (int o = 16; o; o >>= 1) mx = fmaxf(mx, __shfl_xor_sync(0xffffffffu, mx, o));
    if (lid == 0) red[wid] = mx;
    __syncthreads();
    mx = red[0];
    #pragma unroll
    for (int w = 1; w < 8; w++) mx = fmaxf(mx, red[w]);

    float sum = 0.0f;
    #pragma unroll
    for (int i = 0; i < 2; i++) {
        v[i].x = __expf(v[i].x - mx); v[i].y = __expf(v[i].y - mx);
        v[i].z = __expf(v[i].z - mx); v[i].w = __expf(v[i].w - mx);
        sum += (v[i].x + v[i].y) + (v[i].z + v[i].w);
    }
    #pragma unroll
    for (int o = 16; o; o >>= 1) sum += __shfl_xor_sync(0xffffffffu, sum, o);
    __syncthreads();
    if (lid == 0) red[wid] = sum;
    __syncthreads();
    sum = red[0];
    #pragma unroll
    for (int w = 1; w < 8; w++) sum += red[w];
    const float inv = 1.0f / sum;

    #pragma unroll
    for (int i = 0; i < 2; i++) {
        v[i].x *= inv; v[i].y *= inv; v[i].z *= inv; v[i].w *= inv;
    }
    row[tid] = v[0];
    row[tid + 256] = v[1];
}

// ===================== K3: O = P V =====================
#define P_STR 136   // 272B rows: 16B aligned, conflict-free
#define V_STR 72
static const int K3_SMEM = 2 * 128 * P_STR * 2 + 2 * 128 * V_STR * 2;  // 106496 B

__global__ __launch_bounds__(256, 1)
void k3_pv(const float* __restrict__ gp, const float* __restrict__ gv,
           float* __restrict__ gout)
{
    extern __shared__ char smem[];
    char* sPhi = smem;
    char* sPlo = sPhi + 128 * P_STR * 2;
    char* sVhi = sPlo + 128 * P_STR * 2;
    char* sVlo = sVhi + 128 * V_STR * 2;

    const int tid = threadIdx.x, lane = tid & 31, wid = tid >> 5;
    const int qt = blockIdx.x, bh = blockIdx.y;
    const int wm = wid >> 1, wn = wid & 1;

    const float* pp = gp + ((long)bh * NL + qt * 128) * NL;
    const float* vp = gv + (long)bh * NL * ND;

    float d[2][4][4];
    #pragma unroll
    for (int mi = 0; mi < 2; mi++)
        #pragma unroll
        for (int ni = 0; ni < 4; ni++)
            #pragma unroll
            for (int j = 0; j < 4; j++) d[mi][ni][j] = 0.0f;

    const uint32_t phU = smem_u32(sPhi), plU = smem_u32(sPlo);
    const uint32_t vhU = smem_u32(sVhi), vlU = smem_u32(sVlo);
    const int arow = lane & 15, acol = (lane >> 4) << 3;

    for (int t = 0; t < 16; t++) {
        for (int i = tid; i < 4096; i += 256) {  // P: 128 rows x 32 float4
            const int row = i >> 5, c4 = (i & 31) << 2;
            float4 x = *(const float4*)(pp + (long)row * NL + t * 128 + c4);
            uint2 hi, lo;
            cvt_hilo(x, hi, lo);
            const int idx = row * P_STR + c4;
            *(uint2*)(sPhi + idx * 2) = hi; *(uint2*)(sPlo + idx * 2) = lo;
        }
        for (int i = tid; i < 2048; i += 256) {  // V: 128 rows x 16 float4
            const int row = i >> 4, c4 = (i & 15) << 2;
            float4 x = *(const float4*)(vp + (long)(t * 128 + row) * ND + c4);
            uint2 hi, lo;
            cvt_hilo(x, hi, lo);
            const int idx = row * V_STR + c4;
            *(uint2*)(sVhi + idx * 2) = hi; *(uint2*)(sVlo + idx * 2) = lo;
        }
        __syncthreads();

        #pragma unroll
        for (int ks = 0; ks < 8; ks++) {
            const int k0 = ks * 16;
            uint32_t ah[2][4], al[2][4];
            #pragma unroll
            for (int mi = 0; mi < 2; mi++) {
                const uint32_t off = (uint32_t)((wm * 32 + mi * 16 + arow) * P_STR + k0 + acol) * 2;
                ldmx4(phU + off, ah[mi]);
                ldmx4(plU + off, al[mi]);
            }
            uint32_t bh2[4][2], bl2[4][2];
            #pragma unroll
            for (int nb = 0; nb < 2; nb++) {
                // trans fragments from V[k][d]: rows = k, cols = d
                const uint32_t off = (uint32_t)((k0 + arow) * V_STR + wn * 32 + nb * 16 + acol) * 2;
                uint32_t r[4];
                ldmx4t(vhU + off, r);
                bh2[2 * nb][0] = r[0]; bh2[2 * nb][1] = r[1];
                bh2[2 * nb + 1][0] = r[2]; bh2[2 * nb + 1][1] = r[3];
                ldmx4t(vlU + off, r);
                bl2[2 * nb][0] = r[0]; bl2[2 * nb][1] = r[1];
                bl2[2 * nb + 1][0] = r[2]; bl2[2 * nb + 1][1] = r[3];
            }
            #pragma unroll
            for (int mi = 0; mi < 2; mi++)
                #pragma unroll
                for (int ni = 0; ni < 4; ni++) {
                    mma_bf16(d[mi][ni], ah[mi], bh2[ni]);
                    mma_bf16(d[mi][ni], ah[mi], bl2[ni]);
                    mma_bf16(d[mi][ni], al[mi], bh2[ni]);
                }
        }
        __syncthreads();
    }

    const long obase = ((long)bh * NL + qt * 128) * ND;
    #pragma unroll
    for (int mi = 0; mi < 2; mi++)
        #pragma unroll
        for (int ni = 0; ni < 4; ni++) {
            const int r0 = wm * 32 + mi * 16 + (lane >> 2);
            const int c0 = wn * 32 + ni * 8 + ((lane & 3) << 1);
            float2 t0 = {d[mi][ni][0], d[mi][ni][1]};
            float2 t1 = {d[mi][ni][2], d[mi][ni][3]};
            *(float2*)&gout[obase + (long)r0 * ND + c0] = t0;
            *(float2*)&gout[obase + (long)(r0 + 8) * ND + c0] = t1;
        }
}

// ===================== launch =====================
extern "C" void kernel_launch(void* const* d_in, const int* in_sizes, int n_in,
                              void* d_out, int out_size)
{
    (void)in_sizes; (void)n_in; (void)out_size;
    const float* q    = (const float*)d_in[0];
    const float* k    = (const float*)d_in[1];
    const float* v    = (const float*)d_in[2];
    const float* mask = (const float*)d_in[3];
    float* out  = (float*)d_out;
    float* attn = out + (long)NB * NH * NL * ND;  // logits -> probs live here

    cudaFuncSetAttribute(k1_logits, cudaFuncAttributeMaxDynamicSharedMemorySize, K1_SMEM);
    cudaFuncSetAttribute(k3_pv,     cudaFuncAttributeMaxDynamicSharedMemorySize, K3_SMEM);

    dim3 g1(NL / 128, NL / 128, NB * NH);
    k1_logits<<<g1, 256, K1_SMEM>>>(q, k, mask, attn);

    k2_softmax<<<NB * NH * NL, 256>>>(attn);

    dim3 g3(NL / 128, NB * NH);
    k3_pv<<<g3, 256, K3_SMEM>>>(attn, v, out);
}